// round 6
// baseline (speedup 1.0000x reference)
#include <cuda_runtime.h>
#include <cuda_fp16.h>

#define NMAX 50000
#define EMAX 800000

// Scratch (device globals -- no allocation allowed in kernel_launch)
__device__ float  g_agg[NMAX * 64];
__device__ float  g_hA[NMAX * 64];
__device__ float  g_hB[NMAX * 64];
__device__ __half g_x16[NMAX * 64];
__device__ __half g_h16A[NMAX * 64];
__device__ __half g_h16B[NMAX * 64];
__device__ int    g_deg[NMAX];
__device__ int    g_off[NMAX + 1];
__device__ int    g_cur[NMAX];
__device__ int    g_csr[EMAX];
__device__ int    g_bsum[128];

// ---------------- fp32 -> fp16 conversion ----------------

__global__ void k_tofp16(const float* __restrict__ src, __half* __restrict__ dst, int n8) {
    int i = blockIdx.x * blockDim.x + threadIdx.x;
    if (i >= n8) return;
    float4 a = ((const float4*)src)[i * 2];
    float4 b = ((const float4*)src)[i * 2 + 1];
    __half2 h0 = __floats2half2_rn(a.x, a.y);
    __half2 h1 = __floats2half2_rn(a.z, a.w);
    __half2 h2 = __floats2half2_rn(b.x, b.y);
    __half2 h3 = __floats2half2_rn(b.z, b.w);
    uint4 o;
    o.x = reinterpret_cast<unsigned&>(h0);
    o.y = reinterpret_cast<unsigned&>(h1);
    o.z = reinterpret_cast<unsigned&>(h2);
    o.w = reinterpret_cast<unsigned&>(h3);
    ((uint4*)dst)[i] = o;
}

// ---------------- CSR build ----------------

__global__ void k_zero_deg(int n) {
    int i = blockIdx.x * blockDim.x + threadIdx.x;
    if (i < n) g_deg[i] = 0;
}

__global__ void k_count(const int* __restrict__ ei, int e) {
    int i = blockIdx.x * blockDim.x + threadIdx.x;
    if (i < e) atomicAdd(&g_deg[ei[e + i]], 1);   // row 1 of edge_index = dst
}

__global__ void k_blocksum(int n) {
    __shared__ int sm[256];
    int t = threadIdx.x, b = blockIdx.x;
    int base = b * 1024 + t * 4;
    int s = 0;
    #pragma unroll
    for (int u = 0; u < 4; u++) { int i = base + u; if (i < n) s += g_deg[i]; }
    sm[t] = s; __syncthreads();
    #pragma unroll
    for (int o = 128; o; o >>= 1) { if (t < o) sm[t] += sm[t + o]; __syncthreads(); }
    if (t == 0) g_bsum[b] = sm[0];
}

__global__ void k_offsets(int n, int e) {
    __shared__ int sm[256];
    int t = threadIdx.x, b = blockIdx.x;

    int v0 = (t < b) ? g_bsum[t] : 0;
    sm[t] = v0; __syncthreads();
    #pragma unroll
    for (int o = 128; o; o >>= 1) { if (t < o) sm[t] += sm[t + o]; __syncthreads(); }
    int bpre = sm[0];
    __syncthreads();

    int base = b * 1024 + t * 4;
    int vv[4]; int s = 0;
    #pragma unroll
    for (int u = 0; u < 4; u++) { vv[u] = (base + u < n) ? g_deg[base + u] : 0; s += vv[u]; }
    sm[t] = s; __syncthreads();
    #pragma unroll
    for (int o = 1; o < 256; o <<= 1) {
        int val = (t >= o) ? sm[t - o] : 0;
        __syncthreads();
        sm[t] += val;
        __syncthreads();
    }
    int excl = sm[t] - s + bpre;
    #pragma unroll
    for (int u = 0; u < 4; u++) {
        if (base + u < n) { g_off[base + u] = excl; g_cur[base + u] = excl; excl += vv[u]; }
    }
    if (b == 0 && t == 0) g_off[n] = e;
}

__global__ void k_place(const int* __restrict__ ei, int e) {
    int i = blockIdx.x * blockDim.x + threadIdx.x;
    if (i >= e) return;
    int s = ei[i];
    int d = ei[e + i];
    int pos = atomicAdd(&g_cur[d], 1);
    g_csr[pos] = s;
}

// ---------------- mean aggregation: 8 lanes/node, fp16 gather, fp32 accumulate ----------------

__device__ __forceinline__ void addh(float2 acc[4], uint4 v) {
    float2 f;
    f = __half22float2(reinterpret_cast<__half2&>(v.x)); acc[0].x += f.x; acc[0].y += f.y;
    f = __half22float2(reinterpret_cast<__half2&>(v.y)); acc[1].x += f.x; acc[1].y += f.y;
    f = __half22float2(reinterpret_cast<__half2&>(v.z)); acc[2].x += f.x; acc[2].y += f.y;
    f = __half22float2(reinterpret_cast<__half2&>(v.w)); acc[3].x += f.x; acc[3].y += f.y;
}

__global__ void k_aggregate(const __half* __restrict__ h16, int n0, int n1) {
    int t = blockIdx.x * blockDim.x + threadIdx.x;
    int node = n0 + (t >> 3);
    int lane = t & 7;
    if (node >= n1) return;
    int beg = g_off[node];
    int end = g_off[node + 1];

    float2 acc[4];
    acc[0] = acc[1] = acc[2] = acc[3] = make_float2(0.f, 0.f);

    int j = beg;
    for (; j + 3 < end; j += 4) {
        int s0 = __ldg(g_csr + j),     s1 = __ldg(g_csr + j + 1);
        int s2 = __ldg(g_csr + j + 2), s3 = __ldg(g_csr + j + 3);
        uint4 v0 = *(const uint4*)(h16 + (size_t)s0 * 64 + lane * 8);
        uint4 v1 = *(const uint4*)(h16 + (size_t)s1 * 64 + lane * 8);
        uint4 v2 = *(const uint4*)(h16 + (size_t)s2 * 64 + lane * 8);
        uint4 v3 = *(const uint4*)(h16 + (size_t)s3 * 64 + lane * 8);
        addh(acc, v0); addh(acc, v1); addh(acc, v2); addh(acc, v3);
    }
    for (; j < end; j++) {
        int s = __ldg(g_csr + j);
        uint4 v = *(const uint4*)(h16 + (size_t)s * 64 + lane * 8);
        addh(acc, v);
    }
    float inv = 1.0f / fmaxf((float)(end - beg), 1.0f);
    float4 o0 = make_float4(acc[0].x * inv, acc[0].y * inv, acc[1].x * inv, acc[1].y * inv);
    float4 o1 = make_float4(acc[2].x * inv, acc[2].y * inv, acc[3].x * inv, acc[3].y * inv);
    *(float4*)(g_agg + (size_t)node * 64 + lane * 8)     = o0;
    *(float4*)(g_agg + (size_t)node * 64 + lane * 8 + 4) = o1;
}

// ---------------- SAGE transform: 128-row tiles, 8x8 thread tiles ----------------
// out = leaky( [mean_nb | h] @ [Wl; Wr] + bl );  optionally fused output head.

__device__ __forceinline__ unsigned long long pack2(float a) {
    unsigned long long r;
    asm("mov.b64 %0, {%1, %1};" : "=l"(r) : "f"(a));
    return r;
}
__device__ __forceinline__ unsigned long long fma2(unsigned long long a,
                                                   unsigned long long b,
                                                   unsigned long long c) {
    unsigned long long d;
    asm("fma.rn.f32x2 %0, %1, %2, %3;" : "=l"(d) : "l"(a), "l"(b), "l"(c));
    return d;
}

#define ASTRIDE 132
#define SMEM_FLOATS (128 * 64 + 128 * ASTRIDE + 64)

__global__ void __launch_bounds__(128) k_transform(
    const float* __restrict__ h,
    const float* __restrict__ Wl, const float* __restrict__ bl,
    const float* __restrict__ Wr,
    float* __restrict__ out, __half* __restrict__ out16,
    const float* __restrict__ Wo, const float* __restrict__ bo,
    float* __restrict__ outv,
    int n, int tile0, int do_head)
{
    extern __shared__ float smem[];
    float* Bs   = smem;                  // [128][64]: k<64 -> Wl, k>=64 -> Wr
    float* As   = smem + 128 * 64;       // [128][132]
    float* bias = As + 128 * ASTRIDE;    // [64]
    const int tid = threadIdx.x;

    {
        const float4* wl4 = (const float4*)Wl;
        const float4* wr4 = (const float4*)Wr;
        float4* bs4 = (float4*)Bs;
        #pragma unroll
        for (int i = 0; i < 8; i++) {
            bs4[i * 128 + tid]        = wl4[i * 128 + tid];
            bs4[1024 + i * 128 + tid] = wr4[i * 128 + tid];
        }
        if (tid < 16) ((float4*)bias)[tid] = ((const float4*)bl)[tid];
    }

    const int row0 = (tile0 + blockIdx.x) * 128;

    // stage A tile: 4096 float4, 32 per thread
    #pragma unroll
    for (int ii = 0; ii < 32; ii++) {
        int i = ii * 128 + tid;
        int r = i >> 5;
        int q = i & 31;
        int gr = row0 + r;
        float4 v = make_float4(0.f, 0.f, 0.f, 0.f);
        if (gr < n) {
            if (q < 16) v = *(const float4*)(g_agg + (size_t)gr * 64 + q * 4);
            else        v = *(const float4*)(h + (size_t)gr * 64 + (q - 16) * 4);
        }
        *(float4*)(As + r * ASTRIDE + q * 4) = v;
    }
    __syncthreads();

    const int rg = tid >> 3;   // 0..15; rows rg + 16*i (broadcast across 8-lane groups)
    const int cg = tid & 7;    // cols cg*4..+4 and 32+cg*4..+4

    unsigned long long acc[8][4];
    #pragma unroll
    for (int i = 0; i < 8; i++)
        #pragma unroll
        for (int p = 0; p < 4; p++) acc[i][p] = 0ull;

    #pragma unroll 1
    for (int kc = 0; kc < 128; kc += 4) {
        float4 a4[8];
        #pragma unroll
        for (int i = 0; i < 8; i++)
            a4[i] = *(const float4*)(As + (rg + 16 * i) * ASTRIDE + kc);
        #pragma unroll
        for (int kk = 0; kk < 4; kk++) {
            ulonglong2 bb0 = *(const ulonglong2*)(Bs + (kc + kk) * 64 + cg * 4);
            ulonglong2 bb1 = *(const ulonglong2*)(Bs + (kc + kk) * 64 + 32 + cg * 4);
            #pragma unroll
            for (int i = 0; i < 8; i++) {
                float av = ((const float*)&a4[i])[kk];
                unsigned long long aa = pack2(av);
                acc[i][0] = fma2(aa, bb0.x, acc[i][0]);
                acc[i][1] = fma2(aa, bb0.y, acc[i][1]);
                acc[i][2] = fma2(aa, bb1.x, acc[i][2]);
                acc[i][3] = fma2(aa, bb1.y, acc[i][3]);
            }
        }
    }

    float4 bv0 = *(const float4*)(bias + cg * 4);
    float4 bv1 = *(const float4*)(bias + 32 + cg * 4);
    float4 wo0 = make_float4(0.f, 0.f, 0.f, 0.f), wo1 = wo0;
    float bov = 0.f;
    if (do_head) {
        wo0 = *(const float4*)(Wo + cg * 4);
        wo1 = *(const float4*)(Wo + 32 + cg * 4);
        bov = bo[0];
    }

    #pragma unroll
    for (int i = 0; i < 8; i++) {
        int gr = row0 + rg + 16 * i;
        float4 o0, o1;
        asm("mov.b64 {%0, %1}, %2;" : "=f"(o0.x), "=f"(o0.y) : "l"(acc[i][0]));
        asm("mov.b64 {%0, %1}, %2;" : "=f"(o0.z), "=f"(o0.w) : "l"(acc[i][1]));
        asm("mov.b64 {%0, %1}, %2;" : "=f"(o1.x), "=f"(o1.y) : "l"(acc[i][2]));
        asm("mov.b64 {%0, %1}, %2;" : "=f"(o1.z), "=f"(o1.w) : "l"(acc[i][3]));
        o0.x += bv0.x; o0.y += bv0.y; o0.z += bv0.z; o0.w += bv0.w;
        o1.x += bv1.x; o1.y += bv1.y; o1.z += bv1.z; o1.w += bv1.w;
        o0.x = o0.x > 0.f ? o0.x : 0.01f * o0.x;
        o0.y = o0.y > 0.f ? o0.y : 0.01f * o0.y;
        o0.z = o0.z > 0.f ? o0.z : 0.01f * o0.z;
        o0.w = o0.w > 0.f ? o0.w : 0.01f * o0.w;
        o1.x = o1.x > 0.f ? o1.x : 0.01f * o1.x;
        o1.y = o1.y > 0.f ? o1.y : 0.01f * o1.y;
        o1.z = o1.z > 0.f ? o1.z : 0.01f * o1.z;
        o1.w = o1.w > 0.f ? o1.w : 0.01f * o1.w;
        if (do_head) {
            float p = o0.x * wo0.x + o0.y * wo0.y + o0.z * wo0.z + o0.w * wo0.w
                    + o1.x * wo1.x + o1.y * wo1.y + o1.z * wo1.z + o1.w * wo1.w;
            p += __shfl_xor_sync(0xffffffffu, p, 1);
            p += __shfl_xor_sync(0xffffffffu, p, 2);
            p += __shfl_xor_sync(0xffffffffu, p, 4);
            if (cg == 0 && gr < n) outv[gr] = p + bov;
        } else if (gr < n) {
            *(float4*)(out + (size_t)gr * 64 + cg * 4)      = o0;
            *(float4*)(out + (size_t)gr * 64 + 32 + cg * 4) = o1;
            __half2 p0 = __floats2half2_rn(o0.x, o0.y);
            __half2 p1 = __floats2half2_rn(o0.z, o0.w);
            __half2 p2 = __floats2half2_rn(o1.x, o1.y);
            __half2 p3 = __floats2half2_rn(o1.z, o1.w);
            uint2 u0, u1;
            u0.x = reinterpret_cast<unsigned&>(p0);
            u0.y = reinterpret_cast<unsigned&>(p1);
            u1.x = reinterpret_cast<unsigned&>(p2);
            u1.y = reinterpret_cast<unsigned&>(p3);
            *(uint2*)(out16 + (size_t)gr * 64 + cg * 4)      = u0;
            *(uint2*)(out16 + (size_t)gr * 64 + 32 + cg * 4) = u1;
        }
    }
}

extern "C" void kernel_launch(void* const* d_in, const int* in_sizes, int n_in,
                              void* d_out, int out_size)
{
    const float* x   = (const float*)d_in[0];
    const int*   ei  = (const int*)d_in[1];
    const float* W[3][3] = {
        {(const float*)d_in[2], (const float*)d_in[3], (const float*)d_in[4]},
        {(const float*)d_in[5], (const float*)d_in[6], (const float*)d_in[7]},
        {(const float*)d_in[8], (const float*)d_in[9], (const float*)d_in[10]},
    };
    const float* Wo  = (const float*)d_in[11];
    const float* bo  = (const float*)d_in[12];
    float* out = (float*)d_out;

    const int n = in_sizes[0] / 64;
    const int e = in_sizes[1] / 2;

    float *hA = nullptr, *hB = nullptr;
    __half *x16 = nullptr, *h16A = nullptr, *h16B = nullptr;
    cudaGetSymbolAddress((void**)&hA, g_hA);
    cudaGetSymbolAddress((void**)&hB, g_hB);
    cudaGetSymbolAddress((void**)&x16, g_x16);
    cudaGetSymbolAddress((void**)&h16A, g_h16A);
    cudaGetSymbolAddress((void**)&h16B, g_h16B);

    static cudaStream_t s1 = nullptr;
    static cudaEvent_t evF, evX, evA[3], evB;
    if (!s1) {
        cudaStreamCreateWithFlags(&s1, cudaStreamNonBlocking);
        cudaEventCreateWithFlags(&evF, cudaEventDisableTiming);
        cudaEventCreateWithFlags(&evX, cudaEventDisableTiming);
        for (int c = 0; c < 3; c++)
            cudaEventCreateWithFlags(&evA[c], cudaEventDisableTiming);
        cudaEventCreateWithFlags(&evB, cudaEventDisableTiming);
        cudaFuncSetAttribute(k_transform, cudaFuncAttributeMaxDynamicSharedMemorySize,
                             SMEM_FLOATS * 4);
    }

    const int smem_bytes = SMEM_FLOATS * 4;
    const int n8  = n * 8;
    const int cb  = (n8 + 255) / 256;
    const int nb  = (n + 255) / 256;
    const int eb  = (e + 255) / 256;
    const int nbs = (n + 1023) / 1024;

    // chunking: 3 chunks on 128-row tile boundaries
    const int ntiles = (n + 127) / 128;
    int tsz[3];
    tsz[0] = (ntiles + 2) / 3;
    tsz[1] = (ntiles - tsz[0] + 1) / 2;
    tsz[2] = ntiles - tsz[0] - tsz[1];
    int t0[3] = {0, tsz[0], tsz[0] + tsz[1]};

    // fork: x -> fp16 on side stream, CSR build on main
    cudaEventRecord(evF, 0);
    cudaStreamWaitEvent(s1, evF, 0);
    k_tofp16<<<cb, 256, 0, s1>>>(x, x16, n8);
    cudaEventRecord(evX, s1);

    k_zero_deg<<<nb, 256>>>(n);
    k_count<<<eb, 256>>>(ei, e);
    k_blocksum<<<nbs, 256>>>(n);
    k_offsets<<<nbs, 256>>>(n, e);
    k_place<<<eb, 256>>>(ei, e);
    cudaStreamWaitEvent(0, evX, 0);

    // layers: aggregates on main stream, transforms pipelined on s1
    const __half* hin16[3] = {x16, h16A, h16B};
    const float*  hin32[3] = {x,   hA,   hB};
    float*  out32[3]  = {hA,   hB,   nullptr};
    __half* out16p[3] = {h16A, h16B, nullptr};

    for (int l = 0; l < 3; l++) {
        int do_head = (l == 2);
        for (int c = 0; c < 3; c++) {
            if (tsz[c] == 0) { cudaEventRecord(evA[c], 0); continue; }
            int rn0 = t0[c] * 128;
            int rn1 = rn0 + tsz[c] * 128; if (rn1 > n) rn1 = n;
            int ab = ((rn1 - rn0) * 8 + 255) / 256;
            k_aggregate<<<ab, 256>>>(hin16[l], rn0, rn1);
            cudaEventRecord(evA[c], 0);
        }
        for (int c = 0; c < 3; c++) {
            cudaStreamWaitEvent(s1, evA[c], 0);
            if (tsz[c] == 0) continue;
            k_transform<<<tsz[c], 128, smem_bytes, s1>>>(
                hin32[l], W[l][0], W[l][1], W[l][2],
                out32[l], out16p[l], Wo, bo, out, n, t0[c], do_head);
        }
        cudaEventRecord(evB, s1);
        cudaStreamWaitEvent(0, evB, 0);
    }
}

// round 7
// speedup vs baseline: 1.3405x; 1.3405x over previous
#include <cuda_runtime.h>
#include <cuda_fp16.h>

#define NMAX 50000
#define EMAX 800000

// Scratch (device globals -- no allocation allowed in kernel_launch)
__device__ float  g_agg[NMAX * 64];
__device__ float  g_hA[NMAX * 64];
__device__ float  g_hB[NMAX * 64];
__device__ __half g_x16[NMAX * 64];
__device__ __half g_h16A[NMAX * 64];
__device__ __half g_h16B[NMAX * 64];
__device__ int    g_deg[NMAX];
__device__ int    g_off[NMAX + 1];
__device__ int    g_cur[NMAX];
__device__ int    g_csr[EMAX];
__device__ int    g_bsum[128];

// ---------------- fp32 -> fp16 conversion (+ fused deg zeroing) ----------------

__global__ void k_tofp16_zero(const float* __restrict__ src, __half* __restrict__ dst,
                              int n8, int n) {
    int i = blockIdx.x * blockDim.x + threadIdx.x;
    if (i < n) g_deg[i] = 0;
    if (i >= n8) return;
    float4 a = ((const float4*)src)[i * 2];
    float4 b = ((const float4*)src)[i * 2 + 1];
    __half2 h0 = __floats2half2_rn(a.x, a.y);
    __half2 h1 = __floats2half2_rn(a.z, a.w);
    __half2 h2 = __floats2half2_rn(b.x, b.y);
    __half2 h3 = __floats2half2_rn(b.z, b.w);
    uint4 o;
    o.x = reinterpret_cast<unsigned&>(h0);
    o.y = reinterpret_cast<unsigned&>(h1);
    o.z = reinterpret_cast<unsigned&>(h2);
    o.w = reinterpret_cast<unsigned&>(h3);
    ((uint4*)dst)[i] = o;
}

// ---------------- CSR build ----------------

__global__ void k_count(const int* __restrict__ ei, int e) {
    int i = blockIdx.x * blockDim.x + threadIdx.x;
    if (i < e) atomicAdd(&g_deg[ei[e + i]], 1);   // row 1 of edge_index = dst
}

__global__ void k_blocksum(int n) {
    __shared__ int sm[256];
    int t = threadIdx.x, b = blockIdx.x;
    int base = b * 1024 + t * 4;
    int s = 0;
    #pragma unroll
    for (int u = 0; u < 4; u++) { int i = base + u; if (i < n) s += g_deg[i]; }
    sm[t] = s; __syncthreads();
    #pragma unroll
    for (int o = 128; o; o >>= 1) { if (t < o) sm[t] += sm[t + o]; __syncthreads(); }
    if (t == 0) g_bsum[b] = sm[0];
}

__global__ void k_offsets(int n, int e) {
    __shared__ int sm[256];
    int t = threadIdx.x, b = blockIdx.x;

    int v0 = (t < b) ? g_bsum[t] : 0;
    sm[t] = v0; __syncthreads();
    #pragma unroll
    for (int o = 128; o; o >>= 1) { if (t < o) sm[t] += sm[t + o]; __syncthreads(); }
    int bpre = sm[0];
    __syncthreads();

    int base = b * 1024 + t * 4;
    int vv[4]; int s = 0;
    #pragma unroll
    for (int u = 0; u < 4; u++) { vv[u] = (base + u < n) ? g_deg[base + u] : 0; s += vv[u]; }
    sm[t] = s; __syncthreads();
    #pragma unroll
    for (int o = 1; o < 256; o <<= 1) {
        int val = (t >= o) ? sm[t - o] : 0;
        __syncthreads();
        sm[t] += val;
        __syncthreads();
    }
    int excl = sm[t] - s + bpre;
    #pragma unroll
    for (int u = 0; u < 4; u++) {
        if (base + u < n) { g_off[base + u] = excl; g_cur[base + u] = excl; excl += vv[u]; }
    }
    if (b == 0 && t == 0) g_off[n] = e;
}

__global__ void k_place(const int* __restrict__ ei, int e) {
    int i = blockIdx.x * blockDim.x + threadIdx.x;
    if (i >= e) return;
    int s = ei[i];
    int d = ei[e + i];
    int pos = atomicAdd(&g_cur[d], 1);
    g_csr[pos] = s;
}

// ---------------- mean aggregation: 8 lanes/node, fp16 gather, fp32 accumulate ----------------

__device__ __forceinline__ void addh(float2 acc[4], uint4 v) {
    float2 f;
    f = __half22float2(reinterpret_cast<__half2&>(v.x)); acc[0].x += f.x; acc[0].y += f.y;
    f = __half22float2(reinterpret_cast<__half2&>(v.y)); acc[1].x += f.x; acc[1].y += f.y;
    f = __half22float2(reinterpret_cast<__half2&>(v.z)); acc[2].x += f.x; acc[2].y += f.y;
    f = __half22float2(reinterpret_cast<__half2&>(v.w)); acc[3].x += f.x; acc[3].y += f.y;
}

__global__ void k_aggregate(const __half* __restrict__ h16, int n) {
    int t = blockIdx.x * blockDim.x + threadIdx.x;
    int node = t >> 3;
    int lane = t & 7;
    if (node >= n) return;
    int beg = g_off[node];
    int end = g_off[node + 1];

    float2 acc[4];
    acc[0] = acc[1] = acc[2] = acc[3] = make_float2(0.f, 0.f);

    int j = beg;
    for (; j + 3 < end; j += 4) {
        int s0 = __ldg(g_csr + j),     s1 = __ldg(g_csr + j + 1);
        int s2 = __ldg(g_csr + j + 2), s3 = __ldg(g_csr + j + 3);
        uint4 v0 = *(const uint4*)(h16 + (size_t)s0 * 64 + lane * 8);
        uint4 v1 = *(const uint4*)(h16 + (size_t)s1 * 64 + lane * 8);
        uint4 v2 = *(const uint4*)(h16 + (size_t)s2 * 64 + lane * 8);
        uint4 v3 = *(const uint4*)(h16 + (size_t)s3 * 64 + lane * 8);
        addh(acc, v0); addh(acc, v1); addh(acc, v2); addh(acc, v3);
    }
    for (; j < end; j++) {
        int s = __ldg(g_csr + j);
        uint4 v = *(const uint4*)(h16 + (size_t)s * 64 + lane * 8);
        addh(acc, v);
    }
    float inv = 1.0f / fmaxf((float)(end - beg), 1.0f);
    float4 o0 = make_float4(acc[0].x * inv, acc[0].y * inv, acc[1].x * inv, acc[1].y * inv);
    float4 o1 = make_float4(acc[2].x * inv, acc[2].y * inv, acc[3].x * inv, acc[3].y * inv);
    *(float4*)(g_agg + (size_t)node * 64 + lane * 8)     = o0;
    *(float4*)(g_agg + (size_t)node * 64 + lane * 8 + 4) = o1;
}

// ---------------- SAGE transform: 64-row tiles, 8x8 thread tiles, 64 threads ----------------
// out = leaky( [mean_nb | h] @ [Wl; Wr] + bl );  optionally fused output head.

__device__ __forceinline__ unsigned long long pack2(float a) {
    unsigned long long r;
    asm("mov.b64 %0, {%1, %1};" : "=l"(r) : "f"(a));
    return r;
}
__device__ __forceinline__ unsigned long long fma2(unsigned long long a,
                                                   unsigned long long b,
                                                   unsigned long long c) {
    unsigned long long d;
    asm("fma.rn.f32x2 %0, %1, %2, %3;" : "=l"(d) : "l"(a), "l"(b), "l"(c));
    return d;
}

#define ASTRIDE 132
#define SMEM_FLOATS (128 * 64 + 64 * ASTRIDE + 64)

__global__ void __launch_bounds__(64) k_transform(
    const float* __restrict__ h,
    const float* __restrict__ Wl, const float* __restrict__ bl,
    const float* __restrict__ Wr,
    float* __restrict__ out, __half* __restrict__ out16,
    const float* __restrict__ Wo, const float* __restrict__ bo,
    float* __restrict__ outv,
    int n, int do_head)
{
    extern __shared__ float smem[];
    float* Bs   = smem;                 // [128][64]: k<64 -> Wl, k>=64 -> Wr
    float* As   = smem + 128 * 64;      // [64][132]
    float* bias = As + 64 * ASTRIDE;    // [64]
    const int tid = threadIdx.x;

    // stage weights: 2048 float4, 32 per thread
    {
        const float4* wl4 = (const float4*)Wl;
        const float4* wr4 = (const float4*)Wr;
        float4* bs4 = (float4*)Bs;
        #pragma unroll
        for (int i = 0; i < 16; i++) {
            bs4[i * 64 + tid]        = wl4[i * 64 + tid];
            bs4[1024 + i * 64 + tid] = wr4[i * 64 + tid];
        }
        if (tid < 16) ((float4*)bias)[tid] = ((const float4*)bl)[tid];
    }

    const int row0 = blockIdx.x * 64;

    // stage A tile: 2048 float4, 32 per thread
    #pragma unroll
    for (int ii = 0; ii < 32; ii++) {
        int i = ii * 64 + tid;
        int r = i >> 5;
        int q = i & 31;
        int gr = row0 + r;
        float4 v = make_float4(0.f, 0.f, 0.f, 0.f);
        if (gr < n) {
            if (q < 16) v = *(const float4*)(g_agg + (size_t)gr * 64 + q * 4);
            else        v = *(const float4*)(h + (size_t)gr * 64 + (q - 16) * 4);
        }
        *(float4*)(As + r * ASTRIDE + q * 4) = v;
    }
    __syncthreads();

    const int rg = tid >> 3;   // 0..7; rows rg + 8*i (broadcast across 8-lane groups)
    const int cg = tid & 7;    // cols cg*4..+4 and 32+cg*4..+4

    unsigned long long acc[8][4];
    #pragma unroll
    for (int i = 0; i < 8; i++)
        #pragma unroll
        for (int p = 0; p < 4; p++) acc[i][p] = 0ull;

    #pragma unroll 1
    for (int kc = 0; kc < 128; kc += 4) {
        float4 a4[8];
        #pragma unroll
        for (int i = 0; i < 8; i++)
            a4[i] = *(const float4*)(As + (rg + 8 * i) * ASTRIDE + kc);
        #pragma unroll
        for (int kk = 0; kk < 4; kk++) {
            ulonglong2 bb0 = *(const ulonglong2*)(Bs + (kc + kk) * 64 + cg * 4);
            ulonglong2 bb1 = *(const ulonglong2*)(Bs + (kc + kk) * 64 + 32 + cg * 4);
            #pragma unroll
            for (int i = 0; i < 8; i++) {
                float av = ((const float*)&a4[i])[kk];
                unsigned long long aa = pack2(av);
                acc[i][0] = fma2(aa, bb0.x, acc[i][0]);
                acc[i][1] = fma2(aa, bb0.y, acc[i][1]);
                acc[i][2] = fma2(aa, bb1.x, acc[i][2]);
                acc[i][3] = fma2(aa, bb1.y, acc[i][3]);
            }
        }
    }

    float4 bv0 = *(const float4*)(bias + cg * 4);
    float4 bv1 = *(const float4*)(bias + 32 + cg * 4);
    float4 wo0 = make_float4(0.f, 0.f, 0.f, 0.f), wo1 = wo0;
    float bov = 0.f;
    if (do_head) {
        wo0 = *(const float4*)(Wo + cg * 4);
        wo1 = *(const float4*)(Wo + 32 + cg * 4);
        bov = bo[0];
    }

    #pragma unroll
    for (int i = 0; i < 8; i++) {
        int gr = row0 + rg + 8 * i;
        float4 o0, o1;
        asm("mov.b64 {%0, %1}, %2;" : "=f"(o0.x), "=f"(o0.y) : "l"(acc[i][0]));
        asm("mov.b64 {%0, %1}, %2;" : "=f"(o0.z), "=f"(o0.w) : "l"(acc[i][1]));
        asm("mov.b64 {%0, %1}, %2;" : "=f"(o1.x), "=f"(o1.y) : "l"(acc[i][2]));
        asm("mov.b64 {%0, %1}, %2;" : "=f"(o1.z), "=f"(o1.w) : "l"(acc[i][3]));
        o0.x += bv0.x; o0.y += bv0.y; o0.z += bv0.z; o0.w += bv0.w;
        o1.x += bv1.x; o1.y += bv1.y; o1.z += bv1.z; o1.w += bv1.w;
        o0.x = o0.x > 0.f ? o0.x : 0.01f * o0.x;
        o0.y = o0.y > 0.f ? o0.y : 0.01f * o0.y;
        o0.z = o0.z > 0.f ? o0.z : 0.01f * o0.z;
        o0.w = o0.w > 0.f ? o0.w : 0.01f * o0.w;
        o1.x = o1.x > 0.f ? o1.x : 0.01f * o1.x;
        o1.y = o1.y > 0.f ? o1.y : 0.01f * o1.y;
        o1.z = o1.z > 0.f ? o1.z : 0.01f * o1.z;
        o1.w = o1.w > 0.f ? o1.w : 0.01f * o1.w;
        if (do_head) {
            float p = o0.x * wo0.x + o0.y * wo0.y + o0.z * wo0.z + o0.w * wo0.w
                    + o1.x * wo1.x + o1.y * wo1.y + o1.z * wo1.z + o1.w * wo1.w;
            p += __shfl_xor_sync(0xffffffffu, p, 1);
            p += __shfl_xor_sync(0xffffffffu, p, 2);
            p += __shfl_xor_sync(0xffffffffu, p, 4);
            if (cg == 0 && gr < n) outv[gr] = p + bov;
        } else if (gr < n) {
            *(float4*)(out + (size_t)gr * 64 + cg * 4)      = o0;
            *(float4*)(out + (size_t)gr * 64 + 32 + cg * 4) = o1;
            __half2 p0 = __floats2half2_rn(o0.x, o0.y);
            __half2 p1 = __floats2half2_rn(o0.z, o0.w);
            __half2 p2 = __floats2half2_rn(o1.x, o1.y);
            __half2 p3 = __floats2half2_rn(o1.z, o1.w);
            uint2 u0, u1;
            u0.x = reinterpret_cast<unsigned&>(p0);
            u0.y = reinterpret_cast<unsigned&>(p1);
            u1.x = reinterpret_cast<unsigned&>(p2);
            u1.y = reinterpret_cast<unsigned&>(p3);
            *(uint2*)(out16 + (size_t)gr * 64 + cg * 4)      = u0;
            *(uint2*)(out16 + (size_t)gr * 64 + 32 + cg * 4) = u1;
        }
    }
}

extern "C" void kernel_launch(void* const* d_in, const int* in_sizes, int n_in,
                              void* d_out, int out_size)
{
    const float* x   = (const float*)d_in[0];
    const int*   ei  = (const int*)d_in[1];
    const float* Wl1 = (const float*)d_in[2];
    const float* bl1 = (const float*)d_in[3];
    const float* Wr1 = (const float*)d_in[4];
    const float* Wl2 = (const float*)d_in[5];
    const float* bl2 = (const float*)d_in[6];
    const float* Wr2 = (const float*)d_in[7];
    const float* Wl3 = (const float*)d_in[8];
    const float* bl3 = (const float*)d_in[9];
    const float* Wr3 = (const float*)d_in[10];
    const float* Wo  = (const float*)d_in[11];
    const float* bo  = (const float*)d_in[12];
    float* out = (float*)d_out;

    const int n = in_sizes[0] / 64;
    const int e = in_sizes[1] / 2;

    float *hA = nullptr, *hB = nullptr;
    __half *x16 = nullptr, *h16A = nullptr, *h16B = nullptr;
    cudaGetSymbolAddress((void**)&hA, g_hA);
    cudaGetSymbolAddress((void**)&hB, g_hB);
    cudaGetSymbolAddress((void**)&x16, g_x16);
    cudaGetSymbolAddress((void**)&h16A, g_h16A);
    cudaGetSymbolAddress((void**)&h16B, g_h16B);

    const int smem_bytes = SMEM_FLOATS * 4;
    cudaFuncSetAttribute(k_transform, cudaFuncAttributeMaxDynamicSharedMemorySize,
                         smem_bytes);

    const int n8  = n * 8;
    const int cb  = (n8 + 255) / 256;
    const int eb  = (e + 255) / 256;
    const int nbs = (n + 1023) / 1024;
    const int ab  = (n * 8 + 255) / 256;      // aggregate: 8 lanes per node
    const int tb  = (n + 63) / 64;            // transform: 64 rows per block

    // conversion + deg zeroing, then CSR build
    k_tofp16_zero<<<cb, 256>>>(x, x16, n8, n);
    k_count<<<eb, 256>>>(ei, e);
    k_blocksum<<<nbs, 256>>>(n);
    k_offsets<<<nbs, 256>>>(n, e);
    k_place<<<eb, 256>>>(ei, e);

    // layer 1: x -> hA (+h16A)
    k_aggregate<<<ab, 256>>>(x16, n);
    k_transform<<<tb, 64, smem_bytes>>>(x, Wl1, bl1, Wr1, hA, h16A,
                                        nullptr, nullptr, nullptr, n, 0);
    // layer 2: hA -> hB (+h16B)
    k_aggregate<<<ab, 256>>>(h16A, n);
    k_transform<<<tb, 64, smem_bytes>>>(hA, Wl2, bl2, Wr2, hB, h16B,
                                        nullptr, nullptr, nullptr, n, 0);
    // layer 3 + head: hB -> out
    k_aggregate<<<ab, 256>>>(h16B, n);
    k_transform<<<tb, 64, smem_bytes>>>(hB, Wl3, bl3, Wr3, nullptr, nullptr,
                                        Wo, bo, out, n, 1);
}

// round 8
// speedup vs baseline: 1.3753x; 1.0260x over previous
#include <cuda_runtime.h>
#include <cuda_fp16.h>

#define NMAX 50000
#define EMAX 800000

// Scratch (device globals -- no allocation allowed in kernel_launch)
__device__ float  g_agg[NMAX * 64];
__device__ __half g_x16[NMAX * 64];
__device__ __half g_h16A[NMAX * 64];
__device__ __half g_h16B[NMAX * 64];
__device__ int    g_deg[NMAX];
__device__ int    g_off[NMAX + 1];
__device__ int    g_cur[NMAX];
__device__ int    g_csr[EMAX];

// ---------------- fp32 -> fp16 conversion (+ fused deg zeroing) ----------------

__global__ void k_tofp16_zero(const float* __restrict__ src, __half* __restrict__ dst,
                              int n8, int n) {
    int i = blockIdx.x * blockDim.x + threadIdx.x;
    if (i < n) g_deg[i] = 0;
    if (i >= n8) return;
    float4 a = ((const float4*)src)[i * 2];
    float4 b = ((const float4*)src)[i * 2 + 1];
    __half2 h0 = __floats2half2_rn(a.x, a.y);
    __half2 h1 = __floats2half2_rn(a.z, a.w);
    __half2 h2 = __floats2half2_rn(b.x, b.y);
    __half2 h3 = __floats2half2_rn(b.z, b.w);
    uint4 o;
    o.x = reinterpret_cast<unsigned&>(h0);
    o.y = reinterpret_cast<unsigned&>(h1);
    o.z = reinterpret_cast<unsigned&>(h2);
    o.w = reinterpret_cast<unsigned&>(h3);
    ((uint4*)dst)[i] = o;
}

// ---------------- CSR build ----------------

__global__ void k_count(const int* __restrict__ ei, int e) {
    int i = blockIdx.x * blockDim.x + threadIdx.x;
    if (i < e) atomicAdd(&g_deg[ei[e + i]], 1);   // row 1 of edge_index = dst
}

// per-node exclusive offsets; block b directly reduces g_deg[0 .. b*1024) for
// its prefix (no separate blocksum kernel).
__global__ void k_offsets(int n, int e) {
    __shared__ int sm[256];
    int t = threadIdx.x, b = blockIdx.x;

    int total = 0;
    for (int i = t; i < b * 1024; i += 256) total += g_deg[i];
    sm[t] = total; __syncthreads();
    #pragma unroll
    for (int o = 128; o; o >>= 1) { if (t < o) sm[t] += sm[t + o]; __syncthreads(); }
    int bpre = sm[0];
    __syncthreads();

    int base = b * 1024 + t * 4;
    int vv[4]; int s = 0;
    #pragma unroll
    for (int u = 0; u < 4; u++) { vv[u] = (base + u < n) ? g_deg[base + u] : 0; s += vv[u]; }
    sm[t] = s; __syncthreads();
    #pragma unroll
    for (int o = 1; o < 256; o <<= 1) {
        int val = (t >= o) ? sm[t - o] : 0;
        __syncthreads();
        sm[t] += val;
        __syncthreads();
    }
    int excl = sm[t] - s + bpre;
    #pragma unroll
    for (int u = 0; u < 4; u++) {
        if (base + u < n) { g_off[base + u] = excl; g_cur[base + u] = excl; excl += vv[u]; }
    }
    if (b == 0 && t == 0) g_off[n] = e;
}

__global__ void k_place(const int* __restrict__ ei, int e) {
    int i = blockIdx.x * blockDim.x + threadIdx.x;
    if (i >= e) return;
    int s = ei[i];
    int d = ei[e + i];
    int pos = atomicAdd(&g_cur[d], 1);
    g_csr[pos] = s;
}

// ---------------- mean aggregation: 8 lanes/node, fp16 gather, fp32 accumulate ----------------

__device__ __forceinline__ void addh(float2 acc[4], uint4 v) {
    float2 f;
    f = __half22float2(reinterpret_cast<__half2&>(v.x)); acc[0].x += f.x; acc[0].y += f.y;
    f = __half22float2(reinterpret_cast<__half2&>(v.y)); acc[1].x += f.x; acc[1].y += f.y;
    f = __half22float2(reinterpret_cast<__half2&>(v.z)); acc[2].x += f.x; acc[2].y += f.y;
    f = __half22float2(reinterpret_cast<__half2&>(v.w)); acc[3].x += f.x; acc[3].y += f.y;
}

__global__ void k_aggregate(const __half* __restrict__ h16, int n) {
    int t = blockIdx.x * blockDim.x + threadIdx.x;
    int node = t >> 3;
    int lane = t & 7;
    if (node >= n) return;
    int beg = g_off[node];
    int end = g_off[node + 1];

    float2 acc[4];
    acc[0] = acc[1] = acc[2] = acc[3] = make_float2(0.f, 0.f);

    int j = beg;
    for (; j + 3 < end; j += 4) {
        int s0 = __ldg(g_csr + j),     s1 = __ldg(g_csr + j + 1);
        int s2 = __ldg(g_csr + j + 2), s3 = __ldg(g_csr + j + 3);
        uint4 v0 = *(const uint4*)(h16 + (size_t)s0 * 64 + lane * 8);
        uint4 v1 = *(const uint4*)(h16 + (size_t)s1 * 64 + lane * 8);
        uint4 v2 = *(const uint4*)(h16 + (size_t)s2 * 64 + lane * 8);
        uint4 v3 = *(const uint4*)(h16 + (size_t)s3 * 64 + lane * 8);
        addh(acc, v0); addh(acc, v1); addh(acc, v2); addh(acc, v3);
    }
    for (; j < end; j++) {
        int s = __ldg(g_csr + j);
        uint4 v = *(const uint4*)(h16 + (size_t)s * 64 + lane * 8);
        addh(acc, v);
    }
    float inv = 1.0f / fmaxf((float)(end - beg), 1.0f);
    float4 o0 = make_float4(acc[0].x * inv, acc[0].y * inv, acc[1].x * inv, acc[1].y * inv);
    float4 o1 = make_float4(acc[2].x * inv, acc[2].y * inv, acc[3].x * inv, acc[3].y * inv);
    *(float4*)(g_agg + (size_t)node * 64 + lane * 8)     = o0;
    *(float4*)(g_agg + (size_t)node * 64 + lane * 8 + 4) = o1;
}

// ---------------- SAGE transform: persistent weights, grid-stride 32-row tiles ----------------
// out = leaky( [mean_nb | root] @ [Wl; Wr] + bl );  roots from fp16 mirror;
// writes fp16 mirror, or (do_head) the final scalar head.

__device__ __forceinline__ unsigned long long pack2(float a) {
    unsigned long long r;
    asm("mov.b64 %0, {%1, %1};" : "=l"(r) : "f"(a));
    return r;
}
__device__ __forceinline__ unsigned long long fma2(unsigned long long a,
                                                   unsigned long long b,
                                                   unsigned long long c) {
    unsigned long long d;
    asm("fma.rn.f32x2 %0, %1, %2, %3;" : "=l"(d) : "l"(a), "l"(b), "l"(c));
    return d;
}

#define ASTRIDE 132
#define SMEM_FLOATS (128 * 64 + 32 * ASTRIDE + 64)

__global__ void __launch_bounds__(64) k_transform(
    const __half* __restrict__ root16,
    const float* __restrict__ Wl, const float* __restrict__ bl,
    const float* __restrict__ Wr,
    __half* __restrict__ out16,
    const float* __restrict__ Wo, const float* __restrict__ bo,
    float* __restrict__ outv,
    int n, int ntiles, int do_head)
{
    extern __shared__ float smem[];
    float* Bs   = smem;                 // [128][64]: k<64 -> Wl, k>=64 -> Wr
    float* As   = smem + 128 * 64;      // [32][132]
    float* bias = As + 32 * ASTRIDE;    // [64]
    const int tid = threadIdx.x;

    {
        const float4* wl4 = (const float4*)Wl;
        const float4* wr4 = (const float4*)Wr;
        float4* bs4 = (float4*)Bs;
        #pragma unroll
        for (int i = 0; i < 16; i++) {
            bs4[i * 64 + tid]        = wl4[i * 64 + tid];
            bs4[1024 + i * 64 + tid] = wr4[i * 64 + tid];
        }
        if (tid < 16) ((float4*)bias)[tid] = ((const float4*)bl)[tid];
    }

    const int rg = tid >> 4;   // 0..3; rows rg + 4*i
    const int cg = tid & 15;   // cols cg*4..cg*4+3

    float4 wo = make_float4(0.f, 0.f, 0.f, 0.f);
    float bov = 0.f;
    if (do_head) { wo = *(const float4*)(Wo + cg * 4); bov = bo[0]; }

    for (int tile = blockIdx.x; tile < ntiles; tile += gridDim.x) {
        const int row0 = tile * 32;
        if (tile != blockIdx.x) __syncthreads();

        {
            #pragma unroll
            for (int ii = 0; ii < 16; ii++) {
                int i = ii * 64 + tid;
                int r = i >> 5;
                int q = i & 31;
                int gr = row0 + r;
                float4 v = make_float4(0.f, 0.f, 0.f, 0.f);
                if (gr < n) {
                    if (q < 16) {
                        v = *(const float4*)(g_agg + (size_t)gr * 64 + q * 4);
                    } else {
                        uint2 u = *(const uint2*)(root16 + (size_t)gr * 64 + (q - 16) * 4);
                        float2 f0 = __half22float2(reinterpret_cast<__half2&>(u.x));
                        float2 f1 = __half22float2(reinterpret_cast<__half2&>(u.y));
                        v = make_float4(f0.x, f0.y, f1.x, f1.y);
                    }
                }
                *(float4*)(As + r * ASTRIDE + q * 4) = v;
            }
        }
        __syncthreads();

        unsigned long long acc0[8], acc1[8];
        #pragma unroll
        for (int i = 0; i < 8; i++) { acc0[i] = 0ull; acc1[i] = 0ull; }

        #pragma unroll 1
        for (int kc = 0; kc < 128; kc += 4) {
            float4 a4[8];
            #pragma unroll
            for (int i = 0; i < 8; i++)
                a4[i] = *(const float4*)(As + (rg + 4 * i) * ASTRIDE + kc);
            #pragma unroll
            for (int kk = 0; kk < 4; kk++) {
                ulonglong2 bb = *(const ulonglong2*)(Bs + (kc + kk) * 64 + cg * 4);
                #pragma unroll
                for (int i = 0; i < 8; i++) {
                    float av = ((const float*)&a4[i])[kk];
                    unsigned long long aa = pack2(av);
                    acc0[i] = fma2(aa, bb.x, acc0[i]);
                    acc1[i] = fma2(aa, bb.y, acc1[i]);
                }
            }
        }

        float4 bv = *(const float4*)(bias + cg * 4);
        #pragma unroll
        for (int i = 0; i < 8; i++) {
            int gr = row0 + rg + 4 * i;
            float4 o;
            asm("mov.b64 {%0, %1}, %2;" : "=f"(o.x), "=f"(o.y) : "l"(acc0[i]));
            asm("mov.b64 {%0, %1}, %2;" : "=f"(o.z), "=f"(o.w) : "l"(acc1[i]));
            o.x += bv.x; o.y += bv.y; o.z += bv.z; o.w += bv.w;
            o.x = o.x > 0.f ? o.x : 0.01f * o.x;
            o.y = o.y > 0.f ? o.y : 0.01f * o.y;
            o.z = o.z > 0.f ? o.z : 0.01f * o.z;
            o.w = o.w > 0.f ? o.w : 0.01f * o.w;
            if (do_head) {
                float p = o.x * wo.x + o.y * wo.y + o.z * wo.z + o.w * wo.w;
                p += __shfl_xor_sync(0xffffffffu, p, 1);
                p += __shfl_xor_sync(0xffffffffu, p, 2);
                p += __shfl_xor_sync(0xffffffffu, p, 4);
                p += __shfl_xor_sync(0xffffffffu, p, 8);
                if (cg == 0 && gr < n) outv[gr] = p + bov;
            } else if (gr < n) {
                __half2 p0 = __floats2half2_rn(o.x, o.y);
                __half2 p1 = __floats2half2_rn(o.z, o.w);
                uint2 u;
                u.x = reinterpret_cast<unsigned&>(p0);
                u.y = reinterpret_cast<unsigned&>(p1);
                *(uint2*)(out16 + (size_t)gr * 64 + cg * 4) = u;
            }
        }
    }
}

extern "C" void kernel_launch(void* const* d_in, const int* in_sizes, int n_in,
                              void* d_out, int out_size)
{
    const float* x   = (const float*)d_in[0];
    const int*   ei  = (const int*)d_in[1];
    const float* Wl1 = (const float*)d_in[2];
    const float* bl1 = (const float*)d_in[3];
    const float* Wr1 = (const float*)d_in[4];
    const float* Wl2 = (const float*)d_in[5];
    const float* bl2 = (const float*)d_in[6];
    const float* Wr2 = (const float*)d_in[7];
    const float* Wl3 = (const float*)d_in[8];
    const float* bl3 = (const float*)d_in[9];
    const float* Wr3 = (const float*)d_in[10];
    const float* Wo  = (const float*)d_in[11];
    const float* bo  = (const float*)d_in[12];
    float* out = (float*)d_out;

    const int n = in_sizes[0] / 64;
    const int e = in_sizes[1] / 2;

    __half *x16 = nullptr, *h16A = nullptr, *h16B = nullptr;
    cudaGetSymbolAddress((void**)&x16, g_x16);
    cudaGetSymbolAddress((void**)&h16A, g_h16A);
    cudaGetSymbolAddress((void**)&h16B, g_h16B);

    const int smem_bytes = SMEM_FLOATS * 4;
    cudaFuncSetAttribute(k_transform, cudaFuncAttributeMaxDynamicSharedMemorySize,
                         smem_bytes);

    const int n8  = n * 8;
    const int cb  = (n8 + 255) / 256;
    const int eb  = (e + 255) / 256;
    const int nbs = (n + 1023) / 1024;
    const int ab  = (n * 8 + 255) / 256;      // aggregate: 8 lanes per node
    const int ntiles = (n + 31) / 32;
    const int tb  = 592;                      // persistent: 4 blocks per SM

    // conversion (+deg zero), then CSR build
    k_tofp16_zero<<<cb, 256>>>(x, x16, n8, n);
    k_count<<<eb, 256>>>(ei, e);
    k_offsets<<<nbs, 256>>>(n, e);
    k_place<<<eb, 256>>>(ei, e);

    // layer 1: x16 -> h16A
    k_aggregate<<<ab, 256>>>(x16, n);
    k_transform<<<tb, 64, smem_bytes>>>(x16, Wl1, bl1, Wr1, h16A,
                                        nullptr, nullptr, nullptr, n, ntiles, 0);
    // layer 2: h16A -> h16B
    k_aggregate<<<ab, 256>>>(h16A, n);
    k_transform<<<tb, 64, smem_bytes>>>(h16A, Wl2, bl2, Wr2, h16B,
                                        nullptr, nullptr, nullptr, n, ntiles, 0);
    // layer 3 + head: h16B -> out
    k_aggregate<<<ab, 256>>>(h16B, n);
    k_transform<<<tb, 64, smem_bytes>>>(h16B, Wl3, bl3, Wr3, nullptr,
                                        Wo, bo, out, n, ntiles, 1);
}

// round 9
// speedup vs baseline: 1.5175x; 1.1034x over previous
#include <cuda_runtime.h>
#include <cuda_fp16.h>

#define NMAX 50000
#define EMAX 800000

// Scratch (device globals -- no allocation allowed in kernel_launch)
__device__ float  g_agg[NMAX * 64];
__device__ float  g_hA[NMAX * 64];
__device__ float  g_hB[NMAX * 64];
__device__ __half g_x16[NMAX * 64];
__device__ __half g_h16A[NMAX * 64];
__device__ __half g_h16B[NMAX * 64];
__device__ int    g_deg[NMAX];
__device__ int    g_off[NMAX + 1];
__device__ int    g_cur[NMAX];
__device__ int    g_csr[EMAX];
__device__ int    g_bsum[128];

// ---------------- fp32 -> fp16 conversion (+ fused deg zeroing) ----------------

__global__ void k_tofp16_zero(const float* __restrict__ src, __half* __restrict__ dst,
                              int n8, int n) {
    int i = blockIdx.x * blockDim.x + threadIdx.x;
    if (i < n) g_deg[i] = 0;
    if (i >= n8) return;
    float4 a = ((const float4*)src)[i * 2];
    float4 b = ((const float4*)src)[i * 2 + 1];
    __half2 h0 = __floats2half2_rn(a.x, a.y);
    __half2 h1 = __floats2half2_rn(a.z, a.w);
    __half2 h2 = __floats2half2_rn(b.x, b.y);
    __half2 h3 = __floats2half2_rn(b.z, b.w);
    uint4 o;
    o.x = reinterpret_cast<unsigned&>(h0);
    o.y = reinterpret_cast<unsigned&>(h1);
    o.z = reinterpret_cast<unsigned&>(h2);
    o.w = reinterpret_cast<unsigned&>(h3);
    ((uint4*)dst)[i] = o;
}

// ---------------- CSR build ----------------

// 4 edges per thread: 4 independent atomics in flight (hide ATOMG latency)
__global__ void k_count(const int* __restrict__ ei, int e) {
    int i4 = (blockIdx.x * blockDim.x + threadIdx.x) * 4;
    if (i4 >= e) return;
    int cnt = e - i4; if (cnt > 4) cnt = 4;
    int d[4];
    #pragma unroll
    for (int u = 0; u < 4; u++) if (u < cnt) d[u] = __ldg(ei + e + i4 + u);
    #pragma unroll
    for (int u = 0; u < 4; u++) if (u < cnt) atomicAdd(&g_deg[d[u]], 1);
}

__global__ void k_blocksum(int n) {
    __shared__ int sm[256];
    int t = threadIdx.x, b = blockIdx.x;
    int base = b * 1024 + t * 4;
    int s = 0;
    #pragma unroll
    for (int u = 0; u < 4; u++) { int i = base + u; if (i < n) s += g_deg[i]; }
    sm[t] = s; __syncthreads();
    #pragma unroll
    for (int o = 128; o; o >>= 1) { if (t < o) sm[t] += sm[t + o]; __syncthreads(); }
    if (t == 0) g_bsum[b] = sm[0];
}

__global__ void k_offsets(int n, int e) {
    __shared__ int sm[256];
    int t = threadIdx.x, b = blockIdx.x;

    int v0 = (t < b) ? g_bsum[t] : 0;
    sm[t] = v0; __syncthreads();
    #pragma unroll
    for (int o = 128; o; o >>= 1) { if (t < o) sm[t] += sm[t + o]; __syncthreads(); }
    int bpre = sm[0];
    __syncthreads();

    int base = b * 1024 + t * 4;
    int vv[4]; int s = 0;
    #pragma unroll
    for (int u = 0; u < 4; u++) { vv[u] = (base + u < n) ? g_deg[base + u] : 0; s += vv[u]; }
    sm[t] = s; __syncthreads();
    #pragma unroll
    for (int o = 1; o < 256; o <<= 1) {
        int val = (t >= o) ? sm[t - o] : 0;
        __syncthreads();
        sm[t] += val;
        __syncthreads();
    }
    int excl = sm[t] - s + bpre;
    #pragma unroll
    for (int u = 0; u < 4; u++) {
        if (base + u < n) { g_off[base + u] = excl; g_cur[base + u] = excl; excl += vv[u]; }
    }
    if (b == 0 && t == 0) g_off[n] = e;
}

// 4 edges per thread: batch loads, then 4 independent atomics, then 4 scatters
__global__ void k_place(const int* __restrict__ ei, int e) {
    int i4 = (blockIdx.x * blockDim.x + threadIdx.x) * 4;
    if (i4 >= e) return;
    int cnt = e - i4; if (cnt > 4) cnt = 4;
    int s[4], d[4], p[4];
    #pragma unroll
    for (int u = 0; u < 4; u++) if (u < cnt) {
        s[u] = __ldg(ei + i4 + u);
        d[u] = __ldg(ei + e + i4 + u);
    }
    #pragma unroll
    for (int u = 0; u < 4; u++) if (u < cnt) p[u] = atomicAdd(&g_cur[d[u]], 1);
    #pragma unroll
    for (int u = 0; u < 4; u++) if (u < cnt) g_csr[p[u]] = s[u];
}

// ---------------- mean aggregation: 8 lanes/node, fp16 gather, fp32 accumulate ----------------

__device__ __forceinline__ void addh(float2 acc[4], uint4 v) {
    float2 f;
    f = __half22float2(reinterpret_cast<__half2&>(v.x)); acc[0].x += f.x; acc[0].y += f.y;
    f = __half22float2(reinterpret_cast<__half2&>(v.y)); acc[1].x += f.x; acc[1].y += f.y;
    f = __half22float2(reinterpret_cast<__half2&>(v.z)); acc[2].x += f.x; acc[2].y += f.y;
    f = __half22float2(reinterpret_cast<__half2&>(v.w)); acc[3].x += f.x; acc[3].y += f.y;
}

__global__ void k_aggregate(const __half* __restrict__ h16, int n) {
    int t = blockIdx.x * blockDim.x + threadIdx.x;
    int node = t >> 3;
    int lane = t & 7;
    if (node >= n) return;
    int beg = g_off[node];
    int end = g_off[node + 1];

    float2 acc[4];
    acc[0] = acc[1] = acc[2] = acc[3] = make_float2(0.f, 0.f);

    int j = beg;
    for (; j + 7 < end; j += 8) {
        int s0 = __ldg(g_csr + j),     s1 = __ldg(g_csr + j + 1);
        int s2 = __ldg(g_csr + j + 2), s3 = __ldg(g_csr + j + 3);
        int s4 = __ldg(g_csr + j + 4), s5 = __ldg(g_csr + j + 5);
        int s6 = __ldg(g_csr + j + 6), s7 = __ldg(g_csr + j + 7);
        uint4 v0 = *(const uint4*)(h16 + (size_t)s0 * 64 + lane * 8);
        uint4 v1 = *(const uint4*)(h16 + (size_t)s1 * 64 + lane * 8);
        uint4 v2 = *(const uint4*)(h16 + (size_t)s2 * 64 + lane * 8);
        uint4 v3 = *(const uint4*)(h16 + (size_t)s3 * 64 + lane * 8);
        uint4 v4 = *(const uint4*)(h16 + (size_t)s4 * 64 + lane * 8);
        uint4 v5 = *(const uint4*)(h16 + (size_t)s5 * 64 + lane * 8);
        uint4 v6 = *(const uint4*)(h16 + (size_t)s6 * 64 + lane * 8);
        uint4 v7 = *(const uint4*)(h16 + (size_t)s7 * 64 + lane * 8);
        addh(acc, v0); addh(acc, v1); addh(acc, v2); addh(acc, v3);
        addh(acc, v4); addh(acc, v5); addh(acc, v6); addh(acc, v7);
    }
    if (j + 3 < end) {
        int s0 = __ldg(g_csr + j),     s1 = __ldg(g_csr + j + 1);
        int s2 = __ldg(g_csr + j + 2), s3 = __ldg(g_csr + j + 3);
        uint4 v0 = *(const uint4*)(h16 + (size_t)s0 * 64 + lane * 8);
        uint4 v1 = *(const uint4*)(h16 + (size_t)s1 * 64 + lane * 8);
        uint4 v2 = *(const uint4*)(h16 + (size_t)s2 * 64 + lane * 8);
        uint4 v3 = *(const uint4*)(h16 + (size_t)s3 * 64 + lane * 8);
        addh(acc, v0); addh(acc, v1); addh(acc, v2); addh(acc, v3);
        j += 4;
    }
    for (; j < end; j++) {
        int s = __ldg(g_csr + j);
        uint4 v = *(const uint4*)(h16 + (size_t)s * 64 + lane * 8);
        addh(acc, v);
    }
    float inv = 1.0f / fmaxf((float)(end - beg), 1.0f);
    float4 o0 = make_float4(acc[0].x * inv, acc[0].y * inv, acc[1].x * inv, acc[1].y * inv);
    float4 o1 = make_float4(acc[2].x * inv, acc[2].y * inv, acc[3].x * inv, acc[3].y * inv);
    *(float4*)(g_agg + (size_t)node * 64 + lane * 8)     = o0;
    *(float4*)(g_agg + (size_t)node * 64 + lane * 8 + 4) = o1;
}

// ---------------- SAGE transform: persistent weights, grid-stride 32-row tiles ----------------

__device__ __forceinline__ unsigned long long pack2(float a) {
    unsigned long long r;
    asm("mov.b64 %0, {%1, %1};" : "=l"(r) : "f"(a));
    return r;
}
__device__ __forceinline__ unsigned long long fma2(unsigned long long a,
                                                   unsigned long long b,
                                                   unsigned long long c) {
    unsigned long long d;
    asm("fma.rn.f32x2 %0, %1, %2, %3;" : "=l"(d) : "l"(a), "l"(b), "l"(c));
    return d;
}

#define ASTRIDE 132
#define SMEM_FLOATS (128 * 64 + 32 * ASTRIDE + 64)

__global__ void __launch_bounds__(64) k_transform(
    const float* __restrict__ h,
    const float* __restrict__ Wl, const float* __restrict__ bl,
    const float* __restrict__ Wr,
    float* __restrict__ out, __half* __restrict__ out16,
    const float* __restrict__ Wo, const float* __restrict__ bo,
    float* __restrict__ outv,
    int n, int ntiles, int do_head)
{
    extern __shared__ float smem[];
    float* Bs   = smem;                 // [128][64]: k<64 -> Wl, k>=64 -> Wr
    float* As   = smem + 128 * 64;      // [32][132]
    float* bias = As + 32 * ASTRIDE;    // [64]
    const int tid = threadIdx.x;

    {
        const float4* wl4 = (const float4*)Wl;
        const float4* wr4 = (const float4*)Wr;
        float4* bs4 = (float4*)Bs;
        #pragma unroll
        for (int i = 0; i < 16; i++) {
            bs4[i * 64 + tid]        = wl4[i * 64 + tid];
            bs4[1024 + i * 64 + tid] = wr4[i * 64 + tid];
        }
        if (tid < 16) ((float4*)bias)[tid] = ((const float4*)bl)[tid];
    }

    const int rg = tid >> 4;   // 0..3; rows rg + 4*i
    const int cg = tid & 15;   // cols cg*4..cg*4+3

    float4 wo = make_float4(0.f, 0.f, 0.f, 0.f);
    float bov = 0.f;
    if (do_head) { wo = *(const float4*)(Wo + cg * 4); bov = bo[0]; }

    for (int tile = blockIdx.x; tile < ntiles; tile += gridDim.x) {
        const int row0 = tile * 32;
        if (tile != blockIdx.x) __syncthreads();

        {
            #pragma unroll
            for (int ii = 0; ii < 16; ii++) {
                int i = ii * 64 + tid;
                int r = i >> 5;
                int q = i & 31;
                int gr = row0 + r;
                float4 v = make_float4(0.f, 0.f, 0.f, 0.f);
                if (gr < n) {
                    if (q < 16) v = *(const float4*)(g_agg + (size_t)gr * 64 + q * 4);
                    else        v = *(const float4*)(h + (size_t)gr * 64 + (q - 16) * 4);
                }
                *(float4*)(As + r * ASTRIDE + q * 4) = v;
            }
        }
        __syncthreads();

        unsigned long long acc0[8], acc1[8];
        #pragma unroll
        for (int i = 0; i < 8; i++) { acc0[i] = 0ull; acc1[i] = 0ull; }

        #pragma unroll 1
        for (int kc = 0; kc < 128; kc += 4) {
            float4 a4[8];
            #pragma unroll
            for (int i = 0; i < 8; i++)
                a4[i] = *(const float4*)(As + (rg + 4 * i) * ASTRIDE + kc);
            #pragma unroll
            for (int kk = 0; kk < 4; kk++) {
                ulonglong2 bb = *(const ulonglong2*)(Bs + (kc + kk) * 64 + cg * 4);
                #pragma unroll
                for (int i = 0; i < 8; i++) {
                    float av = ((const float*)&a4[i])[kk];
                    unsigned long long aa = pack2(av);
                    acc0[i] = fma2(aa, bb.x, acc0[i]);
                    acc1[i] = fma2(aa, bb.y, acc1[i]);
                }
            }
        }

        float4 bv = *(const float4*)(bias + cg * 4);
        #pragma unroll
        for (int i = 0; i < 8; i++) {
            int gr = row0 + rg + 4 * i;
            float4 o;
            asm("mov.b64 {%0, %1}, %2;" : "=f"(o.x), "=f"(o.y) : "l"(acc0[i]));
            asm("mov.b64 {%0, %1}, %2;" : "=f"(o.z), "=f"(o.w) : "l"(acc1[i]));
            o.x += bv.x; o.y += bv.y; o.z += bv.z; o.w += bv.w;
            o.x = o.x > 0.f ? o.x : 0.01f * o.x;
            o.y = o.y > 0.f ? o.y : 0.01f * o.y;
            o.z = o.z > 0.f ? o.z : 0.01f * o.z;
            o.w = o.w > 0.f ? o.w : 0.01f * o.w;
            if (do_head) {
                float p = o.x * wo.x + o.y * wo.y + o.z * wo.z + o.w * wo.w;
                p += __shfl_xor_sync(0xffffffffu, p, 1);
                p += __shfl_xor_sync(0xffffffffu, p, 2);
                p += __shfl_xor_sync(0xffffffffu, p, 4);
                p += __shfl_xor_sync(0xffffffffu, p, 8);
                if (cg == 0 && gr < n) outv[gr] = p + bov;
            } else if (gr < n) {
                *(float4*)(out + (size_t)gr * 64 + cg * 4) = o;
                __half2 p0 = __floats2half2_rn(o.x, o.y);
                __half2 p1 = __floats2half2_rn(o.z, o.w);
                uint2 u;
                u.x = reinterpret_cast<unsigned&>(p0);
                u.y = reinterpret_cast<unsigned&>(p1);
                *(uint2*)(out16 + (size_t)gr * 64 + cg * 4) = u;
            }
        }
    }
}

extern "C" void kernel_launch(void* const* d_in, const int* in_sizes, int n_in,
                              void* d_out, int out_size)
{
    const float* x   = (const float*)d_in[0];
    const int*   ei  = (const int*)d_in[1];
    const float* Wl1 = (const float*)d_in[2];
    const float* bl1 = (const float*)d_in[3];
    const float* Wr1 = (const float*)d_in[4];
    const float* Wl2 = (const float*)d_in[5];
    const float* bl2 = (const float*)d_in[6];
    const float* Wr2 = (const float*)d_in[7];
    const float* Wl3 = (const float*)d_in[8];
    const float* bl3 = (const float*)d_in[9];
    const float* Wr3 = (const float*)d_in[10];
    const float* Wo  = (const float*)d_in[11];
    const float* bo  = (const float*)d_in[12];
    float* out = (float*)d_out;

    const int n = in_sizes[0] / 64;
    const int e = in_sizes[1] / 2;

    float *hA = nullptr, *hB = nullptr;
    __half *x16 = nullptr, *h16A = nullptr, *h16B = nullptr;
    cudaGetSymbolAddress((void**)&hA, g_hA);
    cudaGetSymbolAddress((void**)&hB, g_hB);
    cudaGetSymbolAddress((void**)&x16, g_x16);
    cudaGetSymbolAddress((void**)&h16A, g_h16A);
    cudaGetSymbolAddress((void**)&h16B, g_h16B);

    const int smem_bytes = SMEM_FLOATS * 4;
    cudaFuncSetAttribute(k_transform, cudaFuncAttributeMaxDynamicSharedMemorySize,
                         smem_bytes);

    const int n8  = n * 8;
    const int cb  = (n8 + 255) / 256;
    const int e4  = (e + 3) / 4;
    const int eb4 = (e4 + 255) / 256;
    const int nbs = (n + 1023) / 1024;
    const int ab  = (n * 8 + 255) / 256;      // aggregate: 8 lanes per node
    const int ntiles = (n + 31) / 32;
    const int tb  = 592;                      // persistent: 4 blocks per SM

    // conversion (+deg zero), then CSR build
    k_tofp16_zero<<<cb, 256>>>(x, x16, n8, n);
    k_count<<<eb4, 256>>>(ei, e);
    k_blocksum<<<nbs, 256>>>(n);
    k_offsets<<<nbs, 256>>>(n, e);
    k_place<<<eb4, 256>>>(ei, e);

    // layer 1: x -> hA (+h16A)
    k_aggregate<<<ab, 256>>>(x16, n);
    k_transform<<<tb, 64, smem_bytes>>>(x, Wl1, bl1, Wr1, hA, h16A,
                                        nullptr, nullptr, nullptr, n, ntiles, 0);
    // layer 2: hA -> hB (+h16B)
    k_aggregate<<<ab, 256>>>(h16A, n);
    k_transform<<<tb, 64, smem_bytes>>>(hA, Wl2, bl2, Wr2, hB, h16B,
                                        nullptr, nullptr, nullptr, n, ntiles, 0);
    // layer 3 + head: hB -> out
    k_aggregate<<<ab, 256>>>(h16B, n);
    k_transform<<<tb, 64, smem_bytes>>>(hB, Wl3, bl3, Wr3, nullptr, nullptr,
                                        Wo, bo, out, n, ntiles, 1);
}